// round 12
// baseline (speedup 1.0000x reference)
#include <cuda_runtime.h>
#include <cuda_bf16.h>

// Problem constants
#define BINS_C   200
#define HW_C     98304          // 256*384
#define NPIX_C   393216         // 4*256*384
#define NPAIR_C  (NPIX_C / 2)   // 196608 pixel-pairs
#define TPB      128
#define NBLK     (NPAIR_C / TPB)   // 1536 blocks (exact, single wave at >=11 CTAs/SM)
#define PRED_ELEMS 78643200     // 4*200*98304
#define STRIDE2  (HW_C / 2)     // channel stride in float2 units

// Per-block packed partials (loss, cnt) + completion counter (wraps to 0 each launch)
__device__ float2   g_part[NBLK];
__device__ unsigned g_done;

// Tap weights exp(-2*d^2), d = 0..4
#define W0T 1.0f
#define W1T 0.13533528f
#define W2T 3.3546263e-4f
#define W3T 1.5229979e-8f
#define W4T 1.2664166e-14f

#define LOG2E_F 1.4426950408889634f

// LUT[k] = weight for dd = k-4 (k=0..8); LUT[9] = 0 (off-window / invalid clamp)
__constant__ float c_lut[10] = {W4T, W3T, W2T, W1T, W0T, W1T, W2T, W3T, W4T, 0.0f};

__device__ __forceinline__ void elem_step(float x, int& idb, float& s, float& dot,
                                          const float* s_lut)
{
    s += exp2f(x * LOG2E_F);                       // FMUL + MUFU.EX2 + FADD
    unsigned ob = (unsigned)idb;
    ob = (ob < 36u) ? ob : 36u;                    // IMNMX.U32 (handles negatives too)
    const float w = *reinterpret_cast<const float*>(
        reinterpret_cast<const char*>(s_lut) + ob); // LDS (<=10 banks, conflict-light)
    dot = __fmaf_rn(w, x, dot);                    // FFMA
    idb += 4;                                      // IADD
}

__device__ __forceinline__ void load8(const float2* __restrict__ pr, int c0, float2 v[8])
{
    #pragma unroll
    for (int u = 0; u < 8; ++u)
        v[u] = __ldcs(&pr[(size_t)(c0 + u) * STRIDE2]);   // evict-first: single-use stream
}

__device__ __forceinline__ void proc8(const float2 v[8], int& i0, int& i1,
                                      float& s0, float& s1, float& dot0, float& dot1,
                                      const float* s_lut)
{
    #pragma unroll
    for (int u = 0; u < 8; ++u) {
        elem_step(v[u].x, i0, s0, dot0, s_lut);
        elem_step(v[u].y, i1, s1, dot1, s_lut);
    }
}

__global__ __launch_bounds__(TPB, 11) void dce_main_kernel(
    const float* __restrict__ target,
    const int*   __restrict__ mask,
    const float* __restrict__ pred,
    float*       __restrict__ out)
{
    __shared__ float s_lut[10];
    if (threadIdx.x < 10) s_lut[threadIdx.x] = c_lut[threadIdx.x];

    const int pair = blockIdx.x * TPB + threadIdx.x;   // pixel-pair index
    const int pix  = pair << 1;
    const int b    = pix / HW_C;
    const int p    = pix - b * HW_C;

    // pred[b, c, p..p+1] as float2
    const float2* __restrict__ pr =
        reinterpret_cast<const float2*>(pred) +
        ((size_t)b * BINS_C * STRIDE2 + (p >> 1));

    const float2 tg = reinterpret_cast<const float2*>(target)[pair];
    const int2   mk = reinterpret_cast<const int2*>(mask)[pair];

    // Start the pred stream IMMEDIATELY: batches 0 and 1 (16 LDG.64 in flight)
    // cover the prologue's dependent bin/rowsum chain below.
    float2 A[8], B[8];
    load8(pr, 0, A);
    load8(pr, 8, B);

    const float INTERVAL_F = 0.0095154499349597177f;  // log10(80)/200 in fp32
    const float WT[5] = {W0T, W1T, W2T, W3T, W4T};

    float tv[2] = {tg.x, tg.y};
    int   mv[2] = {mk.x, mk.y};
    int   idb[2];    // byte index into LUT: (4 - gt + c)*4, advanced per channel
    float rs[2];
    int   cnt = 0;

    #pragma unroll
    for (int j = 0; j < 2; ++j) {
        const bool valid = (mv[j] != 0);   // also correct if mask arrives as f32 0/1
        cnt += valid ? 1 : 0;
        const float d = tv[j];
        int bin = (int)(log10f(fabsf(d)) / INTERVAL_F);  // trunc toward 0, matches .to(int)
        if (d <= 1.0f)      bin = 0;
        if (d >= 80.0f)     bin = BINS_C - 1;
        if (bin == BINS_C)  bin = BINS_C - 1;
        if (!valid)         bin = 1 << 20;  // sentinel: index clamps to LUT[9]=0 forever

        // analytic rowsum of the (edge-truncated) gaussian row; 0 for invalid
        float r = 0.0f;
        #pragma unroll
        for (int dt = -4; dt <= 4; ++dt) {
            const int c = bin + dt;
            if (c >= 0 && c < BINS_C) r += WT[dt < 0 ? -dt : dt];
        }
        rs[j] = r;
        idb[j] = (4 - bin) * 4;
    }

    __syncthreads();   // LUT visible

    float s0 = 0.f, s1 = 0.f, dot0 = 0.f, dot1 = 0.f;
    int  i0 = idb[0], i1 = idb[1];

    // Steady state: batches 0..21 in the loop, each buffer reloads right after use.
    #pragma unroll 1
    for (int k = 0; k < 11; ++k) {
        const int c = k * 16;
        proc8(A, i0, i1, s0, s1, dot0, dot1, s_lut);   // batch 2k
        load8(pr, c + 16, A);                          // batch 2k+2
        proc8(B, i0, i1, s0, s1, dot0, dot1, s_lut);   // batch 2k+1
        load8(pr, c + 24, B);                          // batch 2k+3 (k=10 -> chan 184, last B)
    }
    // Tail: batches 22, 24 (A), 23 (B)
    proc8(A, i0, i1, s0, s1, dot0, dot1, s_lut);       // batch 22 (chan 176-183)
    load8(pr, 192, A);                                  // batch 24 (chan 192-199)
    proc8(B, i0, i1, s0, s1, dot0, dot1, s_lut);       // batch 23 (chan 184-191)
    proc8(A, i0, i1, s0, s1, dot0, dot1, s_lut);       // batch 24

    float loss = __fmaf_rn(rs[0], __logf(s0), -dot0)
               + __fmaf_rn(rs[1], __logf(s1), -dot1);

    // deterministic block reduction (packed loss+cnt)
    __shared__ float2 sp[TPB];
    const int t = threadIdx.x;
    sp[t] = make_float2(loss, (float)cnt);   // cnt <= 256, exact in fp32
    __syncthreads();
    #pragma unroll
    for (int off = TPB / 2; off > 0; off >>= 1) {
        if (t < off) {
            sp[t].x += sp[t + off].x;
            sp[t].y += sp[t + off].y;
        }
        __syncthreads();
    }

    __shared__ bool amLast;
    if (t == 0) {
        g_part[blockIdx.x] = sp[0];
        __threadfence();
        unsigned ticket = atomicInc(&g_done, NBLK - 1);  // wraps to 0 after last block
        amLast = (ticket == NBLK - 1);
    }
    __syncthreads();

    if (amLast) {
        // 1536 packed partials, 128 threads -> 12 vector loads each (deterministic)
        float l = 0.0f, c = 0.0f;
        #pragma unroll
        for (int k = 0; k < NBLK / TPB; ++k) {
            const float2 v = __ldcg(&g_part[t + k * TPB]);   // L2: sees other SMs' writes
            l += v.x;
            c += v.y;
        }
        sp[t] = make_float2(l, c);
        __syncthreads();
        #pragma unroll
        for (int off = TPB / 2; off > 0; off >>= 1) {
            if (t < off) {
                sp[t].x += sp[t + off].x;
                sp[t].y += sp[t + off].y;
            }
            __syncthreads();
        }
        if (t == 0) out[0] = sp[0].x / (sp[0].y + 1e-6f);   // LOSS_WEIGHT = 1
    }
}

extern "C" void kernel_launch(void* const* d_in, const int* in_sizes, int n_in,
                              void* d_out, int out_size)
{
    // Identify inputs by element count (dict order: target, mask, pred_logit, bins_weight)
    const float* target = nullptr;
    const int*   mask   = nullptr;
    const float* pred   = nullptr;
    int small_seen = 0;
    for (int i = 0; i < n_in; ++i) {
        if (in_sizes[i] == NPIX_C) {
            if (small_seen == 0) target = (const float*)d_in[i];
            else                 mask   = (const int*)d_in[i];
            ++small_seen;
        } else if (in_sizes[i] == PRED_ELEMS) {
            pred = (const float*)d_in[i];
        }
        // bins_weight (40000 elems) intentionally unused: weights computed analytically
    }

    dce_main_kernel<<<NBLK, TPB>>>(target, mask, pred, (float*)d_out);
}

// round 13
// speedup vs baseline: 1.3889x; 1.3889x over previous
#include <cuda_runtime.h>
#include <cuda_bf16.h>

// Problem constants
#define BINS_C   200
#define HW_C     98304          // 256*384
#define NPIX_C   393216         // 4*256*384
#define NPAIR_C  (NPIX_C / 2)   // 196608 pixel-pairs
#define TPB      128
#define NBLK     (NPAIR_C / TPB)   // 1536 blocks (exact, single wave at >=11 CTAs/SM)
#define PRED_ELEMS 78643200     // 4*200*98304
#define STRIDE2  (HW_C / 2)     // channel stride in float2 units

// Per-block packed partials (loss, cnt) + completion counter (wraps to 0 each launch)
__device__ float2   g_part[NBLK];
__device__ unsigned g_done;

// Tap weights exp(-2*d^2), d = 0..4
#define W0T 1.0f
#define W1T 0.13533528f
#define W2T 3.3546263e-4f
#define W3T 1.5229979e-8f
#define W4T 1.2664166e-14f

#define LOG2E_F 1.4426950408889634f

// LUT[k] = weight for dd = k-4 (k=0..8); LUT[9] = 0 (off-window / invalid clamp)
__constant__ float c_lut[10] = {W4T, W3T, W2T, W1T, W0T, W1T, W2T, W3T, W4T, 0.0f};

__device__ __forceinline__ void elem_step(float x, int& idb, float& s, float& dot,
                                          const float* s_lut)
{
    s += exp2f(x * LOG2E_F);                       // FMUL + MUFU.EX2 + FADD
    unsigned ob = (unsigned)idb;
    ob = (ob < 36u) ? ob : 36u;                    // IMNMX.U32 (handles negatives too)
    const float w = *reinterpret_cast<const float*>(
        reinterpret_cast<const char*>(s_lut) + ob); // LDS (<=10 banks, conflict-light)
    dot = __fmaf_rn(w, x, dot);                    // FFMA
    idb += 4;                                      // IADD
}

__device__ __forceinline__ void load8(const float2* __restrict__ pr, int c0, float2 v[8])
{
    #pragma unroll
    for (int u = 0; u < 8; ++u)
        v[u] = __ldcs(&pr[(size_t)(c0 + u) * STRIDE2]);   // evict-first: single-use stream
}

__device__ __forceinline__ void proc8(const float2 v[8], int& i0, int& i1,
                                      float& s0, float& s1, float& dot0, float& dot1,
                                      const float* s_lut)
{
    #pragma unroll
    for (int u = 0; u < 8; ++u) {
        elem_step(v[u].x, i0, s0, dot0, s_lut);
        elem_step(v[u].y, i1, s1, dot1, s_lut);
    }
}

__global__ __launch_bounds__(TPB, 11) void dce_main_kernel(
    const float* __restrict__ target,
    const int*   __restrict__ mask,
    const float* __restrict__ pred,
    float*       __restrict__ out)
{
    __shared__ float s_lut[10];
    if (threadIdx.x < 10) s_lut[threadIdx.x] = c_lut[threadIdx.x];

    const int pair = blockIdx.x * TPB + threadIdx.x;   // pixel-pair index
    const int pix  = pair << 1;
    const int b    = pix / HW_C;
    const int p    = pix - b * HW_C;

    // pred[b, c, p..p+1] as float2
    const float2* __restrict__ pr =
        reinterpret_cast<const float2*>(pred) +
        ((size_t)b * BINS_C * STRIDE2 + (p >> 1));

    const float2 tg = reinterpret_cast<const float2*>(target)[pair];
    const int2   mk = reinterpret_cast<const int2*>(mask)[pair];

    // Prologue-overlap-lite: ONLY batch 0 (16 regs) hoisted above the bin chain,
    // so the buffer doesn't compete with prologue liveness (R12's mistake).
    float2 A[8], B[8];
    load8(pr, 0, A);

    const float INTERVAL_F = 0.0095154499349597177f;  // log10(80)/200 in fp32
    const float WT[5] = {W0T, W1T, W2T, W3T, W4T};

    float tv[2] = {tg.x, tg.y};
    int   mv[2] = {mk.x, mk.y};
    int   idb[2];    // byte index into LUT: (4 - gt + c)*4, advanced per channel
    float rs[2];
    int   cnt = 0;

    #pragma unroll
    for (int j = 0; j < 2; ++j) {
        const bool valid = (mv[j] != 0);   // also correct if mask arrives as f32 0/1
        cnt += valid ? 1 : 0;
        const float d = tv[j];
        int bin = (int)(log10f(fabsf(d)) / INTERVAL_F);  // trunc toward 0, matches .to(int)
        if (d <= 1.0f)      bin = 0;
        if (d >= 80.0f)     bin = BINS_C - 1;
        if (bin == BINS_C)  bin = BINS_C - 1;
        if (!valid)         bin = 1 << 20;  // sentinel: index clamps to LUT[9]=0 forever

        // analytic rowsum of the (edge-truncated) gaussian row; 0 for invalid
        float r = 0.0f;
        #pragma unroll
        for (int dt = -4; dt <= 4; ++dt) {
            const int c = bin + dt;
            if (c >= 0 && c < BINS_C) r += WT[dt < 0 ? -dt : dt];
        }
        rs[j] = r;
        idb[j] = (4 - bin) * 4;
    }

    __syncthreads();   // LUT visible

    float s0 = 0.f, s1 = 0.f, dot0 = 0.f, dot1 = 0.f;
    int  i0 = idb[0], i1 = idb[1];

    // R9/R11-proven steady state: 25 batches of 8 channels, double-buffered.
    #pragma unroll 1
    for (int k = 0; k < 12; ++k) {         // steady state: batches 2k .. 2k+1
        const int c = k * 16;
        load8(pr, c + 8, B);               // batch 2k+1
        proc8(A, i0, i1, s0, s1, dot0, dot1, s_lut);   // batch 2k
        load8(pr, c + 16, A);              // batch 2k+2 (k=11 -> chan 192, last)
        proc8(B, i0, i1, s0, s1, dot0, dot1, s_lut);   // batch 2k+1
    }
    proc8(A, i0, i1, s0, s1, dot0, dot1, s_lut);       // batch 24 (chan 192-199)

    float loss = __fmaf_rn(rs[0], __logf(s0), -dot0)
               + __fmaf_rn(rs[1], __logf(s1), -dot1);

    // deterministic block reduction (packed loss+cnt)
    __shared__ float2 sp[TPB];
    const int t = threadIdx.x;
    sp[t] = make_float2(loss, (float)cnt);   // cnt <= 256, exact in fp32
    __syncthreads();
    #pragma unroll
    for (int off = TPB / 2; off > 0; off >>= 1) {
        if (t < off) {
            sp[t].x += sp[t + off].x;
            sp[t].y += sp[t + off].y;
        }
        __syncthreads();
    }

    __shared__ bool amLast;
    if (t == 0) {
        g_part[blockIdx.x] = sp[0];
        __threadfence();
        unsigned ticket = atomicInc(&g_done, NBLK - 1);  // wraps to 0 after last block
        amLast = (ticket == NBLK - 1);
    }
    __syncthreads();

    if (amLast) {
        // 1536 packed partials, 128 threads -> 12 vector loads each (deterministic)
        float l = 0.0f, c = 0.0f;
        #pragma unroll
        for (int k = 0; k < NBLK / TPB; ++k) {
            const float2 v = __ldcg(&g_part[t + k * TPB]);   // L2: sees other SMs' writes
            l += v.x;
            c += v.y;
        }
        sp[t] = make_float2(l, c);
        __syncthreads();
        #pragma unroll
        for (int off = TPB / 2; off > 0; off >>= 1) {
            if (t < off) {
                sp[t].x += sp[t + off].x;
                sp[t].y += sp[t + off].y;
            }
            __syncthreads();
        }
        if (t == 0) out[0] = sp[0].x / (sp[0].y + 1e-6f);   // LOSS_WEIGHT = 1
    }
}

extern "C" void kernel_launch(void* const* d_in, const int* in_sizes, int n_in,
                              void* d_out, int out_size)
{
    // Identify inputs by element count (dict order: target, mask, pred_logit, bins_weight)
    const float* target = nullptr;
    const int*   mask   = nullptr;
    const float* pred   = nullptr;
    int small_seen = 0;
    for (int i = 0; i < n_in; ++i) {
        if (in_sizes[i] == NPIX_C) {
            if (small_seen == 0) target = (const float*)d_in[i];
            else                 mask   = (const int*)d_in[i];
            ++small_seen;
        } else if (in_sizes[i] == PRED_ELEMS) {
            pred = (const float*)d_in[i];
        }
        // bins_weight (40000 elems) intentionally unused: weights computed analytically
    }

    dce_main_kernel<<<NBLK, TPB>>>(target, mask, pred, (float*)d_out);
}